// round 12
// baseline (speedup 1.0000x reference)
#include <cuda_runtime.h>

// Embed3D: out[nl, p*40 + 2k + {0,1}] = {sin, cos}(x[nl,1+p] * div_term[k])
// x: (NL,4) fp32, div_term: 20 fp32, out: (NL,120) fp32, NL = 64*8192 = 524288.
//
// Champion recipe (R3/R10) at doubled block granularity:
// blockDim=960 (30 full warps), j = tid%30 (float4 slot), r = tid/30
// (row 0..31 per slice), 8 slices -> 256 rows/block, grid 2048.
// Per-slice block store = 15360B contiguous STG.128 .cs.
// __launch_bounds__(960,2) pins 2 CTA/SM = 60 resident warps (same as champion).

#define THREADS 960
#define ROWS_PER_SLICE 32
#define SLICES 8
#define ROWS_PER_BLOCK (ROWS_PER_SLICE * SLICES)   // 256

__device__ __forceinline__ void stg_cs_v4(float4* ptr, float4 v) {
    asm volatile("st.global.cs.v4.f32 [%0], {%1, %2, %3, %4};"
                 :: "l"(ptr), "f"(v.x), "f"(v.y), "f"(v.z), "f"(v.w)
                 : "memory");
}

__global__ __launch_bounds__(THREADS, 2)
void embed3d_kernel(const float* __restrict__ x,
                    const float* __restrict__ div_term,
                    float* __restrict__ out,
                    int total_nl) {
    const int tid = threadIdx.x;
    const int j   = tid % 30;          // float4 slot within a row
    const int r   = tid / 30;          // row within slice (0..31)

    const int p = j / 10;              // pos component 0..2
    const int q = j - p * 10;          // pair group 0..9

    const float d0 = __ldg(&div_term[2 * q]);
    const float d1 = __ldg(&div_term[2 * q + 1]);

    const int nl_base = blockIdx.x * ROWS_PER_BLOCK + r;

    // Batch all pos loads up front: 8 independent LDGs in flight.
    float pos[SLICES];
#pragma unroll
    for (int s = 0; s < SLICES; s++) {
        const int nl = nl_base + s * ROWS_PER_SLICE;
        pos[s] = __ldg(&x[nl * 4 + 1 + p]);
    }

#pragma unroll
    for (int s = 0; s < SLICES; s++) {
        const int nl = nl_base + s * ROWS_PER_SLICE;
        float4 v;
        __sincosf(pos[s] * d0, &v.x, &v.y);
        __sincosf(pos[s] * d1, &v.z, &v.w);
        stg_cs_v4(reinterpret_cast<float4*>(out) + nl * 30 + j, v);
    }
}

extern "C" void kernel_launch(void* const* d_in, const int* in_sizes, int n_in,
                              void* d_out, int out_size) {
    const float* x        = (const float*)d_in[0];
    const float* div_term = (const float*)d_in[1];
    float* out            = (float*)d_out;

    const int total_nl = in_sizes[0] / 4;           // 524288, divisible by 256
    const int grid = total_nl / ROWS_PER_BLOCK;     // 2048

    embed3d_kernel<<<grid, THREADS>>>(x, div_term, out, total_nl);
}